// round 4
// baseline (speedup 1.0000x reference)
#include <cuda_runtime.h>

#define N_NODES 10000
#define N_EDGES 640000
#define D_FEAT  128
#define GRID_L  ((N_NODES + 63) / 64)   // 157 tiles of 64 nodes

// ---------------- scratch (static device globals; no allocations) ----------------
__device__ __align__(256) float g_dinv[N_NODES];
__device__ __align__(256) int   g_count[N_NODES];
__device__ __align__(256) int   g_cur[N_NODES];
__device__ __align__(256) int   g_off[N_NODES + 1];
__device__ __align__(256) int2  g_csr[N_EDGES];          // {src, float bits of weight}
__device__ __align__(256) float g_bufA[N_NODES * D_FEAT];
__device__ __align__(256) float g_bufB[N_NODES * D_FEAT];
__device__ int g_is64;

// ---------------- packed f32x2 helpers (sm_100a) ----------------
__device__ __forceinline__ unsigned long long pack2(float x, float y) {
    unsigned long long r;
    asm("mov.b64 %0, {%1, %2};" : "=l"(r) : "f"(x), "f"(y));
    return r;
}
__device__ __forceinline__ void unpack2(unsigned long long v, float& x, float& y) {
    asm("mov.b64 {%0, %1}, %2;" : "=f"(x), "=f"(y) : "l"(v));
}
__device__ __forceinline__ void ffma2(unsigned long long& c,
                                      unsigned long long a, unsigned long long b) {
    asm("fma.rn.f32x2 %0, %1, %2, %0;" : "+l"(c) : "l"(a), "l"(b));
}

// ---------------- structure kernels ----------------

// zero counters + dtype-detect (warp 0 of block 0).
// int64 edge_index => every odd 32-bit word is 0 (values < 2^31).
__global__ void k_init(const int* __restrict__ ei32) {
    int t = threadIdx.x;
    int i = blockIdx.x * blockDim.x + t;
    if (i < N_NODES) { g_count[i] = 0; g_cur[i] = 0; }
    if (blockIdx.x == 0 && t < 32) {
        int any = 0;
#pragma unroll 8
        for (int k = 0; k < 32; k++) any |= ei32[2 * (t * 32 + k) + 1];
        int is64 = __any_sync(0xffffffffu, any != 0) ? 0 : 1;
        if (t == 0) g_is64 = is64;
    }
}

__device__ __forceinline__ int load_ei(const void* ei, int idx) {
    if (g_is64) return (int)((const long long*)ei)[idx];
    return ((const int*)ei)[idx];
}

__global__ void k_hist(const void* __restrict__ ei) {
    int i = blockIdx.x * blockDim.x + threadIdx.x;
    if (i < N_EDGES) {
        int d = load_ei(ei, N_EDGES + i);   // row 1 = dst
        if ((unsigned)d < N_NODES) atomicAdd(&g_count[d], 1);
    }
}

// single-block exclusive scan of g_count -> g_off, plus dinv
__global__ void k_scan() {
    __shared__ int part[1024];
    const int CH = 10;
    int t = threadIdx.x;
    int base = t * CH;
    int s = 0;
#pragma unroll
    for (int i = 0; i < CH; i++) {
        int idx = base + i;
        if (idx < N_NODES) s += g_count[idx];
    }
    part[t] = s;
    __syncthreads();
    for (int d = 1; d < 1024; d <<= 1) {
        int v = (t >= d) ? part[t - d] : 0;
        __syncthreads();
        part[t] += v;
        __syncthreads();
    }
    int run = (t == 0) ? 0 : part[t - 1];
#pragma unroll
    for (int i = 0; i < CH; i++) {
        int idx = base + i;
        if (idx < N_NODES) {
            int c = g_count[idx];
            g_off[idx] = run;
            run += c;
            g_dinv[idx] = rsqrtf((float)(c + 1));   // +1 self-loop
        } else if (idx == N_NODES) {
            g_off[N_NODES] = run;
        }
    }
}

__global__ void k_scatter(const void* __restrict__ ei) {
    int i = blockIdx.x * blockDim.x + threadIdx.x;
    if (i < N_EDGES) {
        int s = load_ei(ei, i);
        int d = load_ei(ei, N_EDGES + i);
        if ((unsigned)d < N_NODES) {
            int p = g_off[d] + atomicAdd(&g_cur[d], 1);
            bool sv = (unsigned)s < N_NODES;
            float w = sv ? (g_dinv[s] * g_dinv[d]) : 0.0f;
            g_csr[p] = make_int2(sv ? s : 0, __float_as_int(w));
        }
    }
}

// ---------------- fused layer: aggregate -> GEMM(+bias+relu) [-> GEMM2 for FINAL] ----
// SRC: 0 = external x, 1 = g_bufB, 2 = g_bufA
// DST (non-final): 1 = g_bufB, 2 = g_bufA
// FINAL: also computes out = relu(H) @ W2 + b2 (128 -> 64), writing outp.
template <int SRC, int DST, bool FINAL>
__global__ void __launch_bounds__(256) k_layer(
    const float* __restrict__ xin,
    const float* __restrict__ W,  const float* __restrict__ bias,
    const float* __restrict__ W2, const float* __restrict__ bias2,
    float* __restrict__ outp, int M)
{
    __shared__ float As[128][65];   // k-major aggregated tile (pad 65: 4-way STS max)
    __shared__ float Bs[16][128];   // weight tile

    const float* __restrict__ fin =
        (SRC == 0) ? xin : ((SRC == 1) ? (const float*)g_bufB : (const float*)g_bufA);

    const int t    = threadIdx.x;
    const int wid  = t >> 5;
    const int lane = t & 31;
    const int m0   = blockIdx.x * 64;

    // ---------- phase 1: aggregate 64 destination nodes into As ----------
    // out[v] = dinv[v]^2 * in[v] + sum_e w_e * in[src_e]; lane covers 4 feats (float4)
#pragma unroll 1
    for (int i = 0; i < 8; i++) {
        int mloc = wid * 8 + i;
        int v = m0 + mloc;
        float4 acc = make_float4(0.f, 0.f, 0.f, 0.f);
        if (v < M) {
            float dv = g_dinv[v];
            float4 xv = ((const float4*)(fin + (size_t)v * D_FEAT))[lane];
            float sl = dv * dv;
            acc.x = xv.x * sl; acc.y = xv.y * sl; acc.z = xv.z * sl; acc.w = xv.w * sl;
            int j = g_off[v], end = g_off[v + 1];
            for (; j + 4 <= end; j += 4) {
                int2 e0 = g_csr[j],     e1 = g_csr[j + 1];
                int2 e2 = g_csr[j + 2], e3 = g_csr[j + 3];
                float4 f0 = ((const float4*)(fin + (size_t)e0.x * D_FEAT))[lane];
                float4 f1 = ((const float4*)(fin + (size_t)e1.x * D_FEAT))[lane];
                float4 f2 = ((const float4*)(fin + (size_t)e2.x * D_FEAT))[lane];
                float4 f3 = ((const float4*)(fin + (size_t)e3.x * D_FEAT))[lane];
                float w0 = __int_as_float(e0.y), w1 = __int_as_float(e1.y);
                float w2 = __int_as_float(e2.y), w3 = __int_as_float(e3.y);
                acc.x += w0 * f0.x; acc.y += w0 * f0.y; acc.z += w0 * f0.z; acc.w += w0 * f0.w;
                acc.x += w1 * f1.x; acc.y += w1 * f1.y; acc.z += w1 * f1.z; acc.w += w1 * f1.w;
                acc.x += w2 * f2.x; acc.y += w2 * f2.y; acc.z += w2 * f2.z; acc.w += w2 * f2.w;
                acc.x += w3 * f3.x; acc.y += w3 * f3.y; acc.z += w3 * f3.z; acc.w += w3 * f3.w;
            }
            for (; j < end; j++) {
                int2 e = g_csr[j];
                float w = __int_as_float(e.y);
                float4 f = ((const float4*)(fin + (size_t)e.x * D_FEAT))[lane];
                acc.x += w * f.x; acc.y += w * f.y; acc.z += w * f.z; acc.w += w * f.w;
            }
        }
        As[4 * lane + 0][mloc] = acc.x;
        As[4 * lane + 1][mloc] = acc.y;
        As[4 * lane + 2][mloc] = acc.z;
        As[4 * lane + 3][mloc] = acc.w;
    }
    __syncthreads();

    // ---------- phase 2: C[64,128] = As^T(64x128) @ W(128x128), f32x2 packed ----------
    const int tx = t & 15;          // 16 col groups of 8
    const int ty = t >> 4;          // 16 row groups of 4
    unsigned long long acc2[4][4];
#pragma unroll
    for (int i = 0; i < 4; i++)
#pragma unroll
        for (int j = 0; j < 4; j++) acc2[i][j] = 0ull;

    for (int k0 = 0; k0 < 128; k0 += 16) {
#pragma unroll
        for (int i = 0; i < 2; i++) {
            int idx = t + i * 256;            // 512 float4 total
            int rr = idx >> 5;                // /32
            int cc = (idx & 31) * 4;
            *(float4*)&Bs[rr][cc] = *(const float4*)(W + (size_t)(k0 + rr) * 128 + cc);
        }
        __syncthreads();
#pragma unroll
        for (int kk = 0; kk < 16; kk++) {
            unsigned long long ap[4], bv[4];
#pragma unroll
            for (int i = 0; i < 4; i++) {
                float a = As[k0 + kk][ty * 4 + i];
                ap[i] = pack2(a, a);
            }
#pragma unroll
            for (int j = 0; j < 4; j++)
                bv[j] = *(const unsigned long long*)&Bs[kk][tx * 8 + 2 * j];
#pragma unroll
            for (int i = 0; i < 4; i++)
#pragma unroll
                for (int j = 0; j < 4; j++) ffma2(acc2[i][j], ap[i], bv[j]);
        }
        __syncthreads();
    }

    if (!FINAL) {
        float* __restrict__ C = (DST == 1) ? g_bufB : g_bufA;
#pragma unroll
        for (int i = 0; i < 4; i++) {
            int gm = m0 + ty * 4 + i;
            if (gm >= M) continue;
            float o[8];
#pragma unroll
            for (int j = 0; j < 4; j++) {
                float lo, hi; unpack2(acc2[i][j], lo, hi);
                int col = tx * 8 + 2 * j;
                o[2 * j]     = fmaxf(lo + bias[col], 0.f);
                o[2 * j + 1] = fmaxf(hi + bias[col + 1], 0.f);
            }
            *(float4*)(C + (size_t)gm * 128 + tx * 8)     = make_float4(o[0], o[1], o[2], o[3]);
            *(float4*)(C + (size_t)gm * 128 + tx * 8 + 4) = make_float4(o[4], o[5], o[6], o[7]);
        }
    } else {
        // write relu(H) back into As (k-major) — all phase-2 As reads are done
#pragma unroll
        for (int i = 0; i < 4; i++) {
            int mloc = ty * 4 + i;
#pragma unroll
            for (int j = 0; j < 4; j++) {
                float lo, hi; unpack2(acc2[i][j], lo, hi);
                int col = tx * 8 + 2 * j;
                As[col][mloc]     = fmaxf(lo + bias[col], 0.f);
                As[col + 1][mloc] = fmaxf(hi + bias[col + 1], 0.f);
            }
        }
        __syncthreads();

        // GEMM2: out[64,64] = H(64x128) @ W2(128x64) + b2
        unsigned long long acc3[4][2];
#pragma unroll
        for (int i = 0; i < 4; i++) { acc3[i][0] = 0ull; acc3[i][1] = 0ull; }

        for (int k0 = 0; k0 < 128; k0 += 16) {
            {
                int rr = t >> 4;               // 16 rows
                int cc = (t & 15) * 4;         // 64 cols
                *(float4*)&Bs[rr][cc] = *(const float4*)(W2 + (size_t)(k0 + rr) * 64 + cc);
            }
            __syncthreads();
#pragma unroll
            for (int kk = 0; kk < 16; kk++) {
                unsigned long long ap[4], bv[2];
#pragma unroll
                for (int i = 0; i < 4; i++) {
                    float a = As[k0 + kk][ty * 4 + i];
                    ap[i] = pack2(a, a);
                }
#pragma unroll
                for (int j = 0; j < 2; j++)
                    bv[j] = *(const unsigned long long*)&Bs[kk][tx * 4 + 2 * j];
#pragma unroll
                for (int i = 0; i < 4; i++)
#pragma unroll
                    for (int j = 0; j < 2; j++) ffma2(acc3[i][j], ap[i], bv[j]);
            }
            __syncthreads();
        }
#pragma unroll
        for (int i = 0; i < 4; i++) {
            int gm = m0 + ty * 4 + i;
            if (gm >= M) continue;
            float o0, o1, o2, o3;
            unpack2(acc3[i][0], o0, o1);
            unpack2(acc3[i][1], o2, o3);
            int col = tx * 4;
            o0 += bias2[col];     o1 += bias2[col + 1];
            o2 += bias2[col + 2]; o3 += bias2[col + 3];
            *(float4*)(outp + (size_t)gm * 64 + col) = make_float4(o0, o1, o2, o3);
        }
    }
}

// ---------------- launch ----------------
extern "C" void kernel_launch(void* const* d_in, const int* in_sizes, int n_in,
                              void* d_out, int out_size) {
    const float* x  = (const float*)d_in[0];
    const void*  ei = d_in[1];
    const float* w1 = (const float*)d_in[2];
    const float* b1 = (const float*)d_in[3];
    const float* w2 = (const float*)d_in[4];
    const float* b2 = (const float*)d_in[5];
    const float* w3 = (const float*)d_in[6];
    const float* b3 = (const float*)d_in[7];
    const float* wo = (const float*)d_in[8];
    const float* bo = (const float*)d_in[9];
    float* out = (float*)d_out;

    const int TB = 256;
    k_init   <<<(N_NODES + TB - 1) / TB, TB>>>((const int*)ei);
    k_hist   <<<(N_EDGES + TB - 1) / TB, TB>>>(ei);
    k_scan   <<<1, 1024>>>();
    k_scatter<<<(N_EDGES + TB - 1) / TB, TB>>>(ei);

    // layer 1: bufB = relu( agg(x) @ W1 + b1 )
    k_layer<0, 1, false><<<GRID_L, TB>>>(x, w1, b1, nullptr, nullptr, nullptr, N_NODES);
    // layer 2: bufA = relu( agg(bufB) @ W2 + b2 )
    k_layer<1, 2, false><<<GRID_L, TB>>>(nullptr, w2, b2, nullptr, nullptr, nullptr, N_NODES);
    // layer 3 + head: out = relu( agg(bufA) @ W3 + b3 ) @ Wout + bout
    k_layer<2, 0, true><<<GRID_L, TB>>>(nullptr, w3, b3, wo, bo, out, N_NODES);
}

// round 5
// speedup vs baseline: 1.1305x; 1.1305x over previous
#include <cuda_runtime.h>

#define N_NODES 10000
#define N_EDGES 640000
#define D_FEAT  128

// ---------------- scratch (static device globals; no allocations) ----------------
__device__ __align__(256) float g_dinv[N_NODES];
__device__ __align__(256) int   g_count[N_NODES];
__device__ __align__(256) int   g_cur[N_NODES];
__device__ __align__(256) int   g_off[N_NODES + 1];
__device__ __align__(256) int2  g_csr[N_EDGES];          // {src, float bits of weight}
__device__ __align__(256) float g_bufA[N_NODES * D_FEAT];
__device__ __align__(256) float g_bufB[N_NODES * D_FEAT];
__device__ int g_is64;

// ---------------- packed f32x2 helpers (sm_100a) ----------------
__device__ __forceinline__ unsigned long long pack2(float x, float y) {
    unsigned long long r;
    asm("mov.b64 %0, {%1, %2};" : "=l"(r) : "f"(x), "f"(y));
    return r;
}
__device__ __forceinline__ void unpack2(unsigned long long v, float& x, float& y) {
    asm("mov.b64 {%0, %1}, %2;" : "=f"(x), "=f"(y) : "l"(v));
}
__device__ __forceinline__ void ffma2(unsigned long long& c,
                                      unsigned long long a, unsigned long long b) {
    asm("fma.rn.f32x2 %0, %1, %2, %0;" : "+l"(c) : "l"(a), "l"(b));
}

// ---------------- structure kernels ----------------

// zero counters + dtype-detect (warp 0 of block 0).
// int64 edge_index => every odd 32-bit word of the src row is 0 (values < 2^31).
__global__ void k_init(const int* __restrict__ ei32) {
    int t = threadIdx.x;
    int i = blockIdx.x * blockDim.x + t;
    if (i < N_NODES) { g_count[i] = 0; g_cur[i] = 0; }
    if (blockIdx.x == 0 && t < 32) {
        int any = 0;
#pragma unroll 8
        for (int k = 0; k < 32; k++) any |= ei32[2 * (t * 32 + k) + 1];
        int is64 = __any_sync(0xffffffffu, any != 0) ? 0 : 1;
        if (t == 0) g_is64 = is64;
    }
}

// histogram of dst row, 2 edges per thread via 128-bit loads
__global__ void k_hist(const void* __restrict__ ei) {
    int i = blockIdx.x * blockDim.x + threadIdx.x;
    if (i < N_EDGES / 2) {
        int d0, d1;
        if (g_is64) {
            longlong2 p = ((const longlong2*)ei)[N_EDGES / 2 + i];
            d0 = (int)p.x; d1 = (int)p.y;
        } else {
            int2 p = ((const int2*)ei)[N_EDGES / 2 + i];
            d0 = p.x; d1 = p.y;
        }
        if ((unsigned)d0 < N_NODES) atomicAdd(&g_count[d0], 1);
        if ((unsigned)d1 < N_NODES) atomicAdd(&g_count[d1], 1);
    }
}

// single-block exclusive scan of g_count -> g_off, plus dinv
__global__ void k_scan() {
    __shared__ int part[1024];
    const int CH = 10;
    int t = threadIdx.x;
    int base = t * CH;
    int s = 0;
#pragma unroll
    for (int i = 0; i < CH; i++) {
        int idx = base + i;
        if (idx < N_NODES) s += g_count[idx];
    }
    part[t] = s;
    __syncthreads();
    for (int d = 1; d < 1024; d <<= 1) {
        int v = (t >= d) ? part[t - d] : 0;
        __syncthreads();
        part[t] += v;
        __syncthreads();
    }
    int run = (t == 0) ? 0 : part[t - 1];
#pragma unroll
    for (int i = 0; i < CH; i++) {
        int idx = base + i;
        if (idx < N_NODES) {
            int c = g_count[idx];
            g_off[idx] = run;
            run += c;
            g_dinv[idx] = rsqrtf((float)(c + 1));   // +1 self-loop
        } else if (idx == N_NODES) {
            g_off[N_NODES] = run;
        }
    }
}

// CSR fill, 2 edges per thread via 128-bit loads
__global__ void k_scatter(const void* __restrict__ ei) {
    int i = blockIdx.x * blockDim.x + threadIdx.x;
    if (i < N_EDGES / 2) {
        int s0, s1, d0, d1;
        if (g_is64) {
            longlong2 ps = ((const longlong2*)ei)[i];
            longlong2 pd = ((const longlong2*)ei)[N_EDGES / 2 + i];
            s0 = (int)ps.x; s1 = (int)ps.y;
            d0 = (int)pd.x; d1 = (int)pd.y;
        } else {
            int2 ps = ((const int2*)ei)[i];
            int2 pd = ((const int2*)ei)[N_EDGES / 2 + i];
            s0 = ps.x; s1 = ps.y;
            d0 = pd.x; d1 = pd.y;
        }
        if ((unsigned)d0 < N_NODES) {
            int p = g_off[d0] + atomicAdd(&g_cur[d0], 1);
            bool sv = (unsigned)s0 < N_NODES;
            float w = sv ? (g_dinv[s0] * g_dinv[d0]) : 0.0f;
            g_csr[p] = make_int2(sv ? s0 : 0, __float_as_int(w));
        }
        if ((unsigned)d1 < N_NODES) {
            int p = g_off[d1] + atomicAdd(&g_cur[d1], 1);
            bool sv = (unsigned)s1 < N_NODES;
            float w = sv ? (g_dinv[s1] * g_dinv[d1]) : 0.0f;
            g_csr[p] = make_int2(sv ? s1 : 0, __float_as_int(w));
        }
    }
}

// ---------------- aggregation: one warp per destination node ----------------
// out[v] = dinv[v]^2 * in[v] + sum_e w_e * in[src_e]
// Input: xin if non-null, else g_bufB. Output: g_bufA. Lane covers 4 feats (float4).
__global__ void __launch_bounds__(256) k_agg(const float* __restrict__ xin) {
    const float* __restrict__ fin = xin ? xin : (const float*)g_bufB;
    float* __restrict__ fout = g_bufA;

    int v    = (blockIdx.x * blockDim.x + threadIdx.x) >> 5;
    int lane = threadIdx.x & 31;
    if (v >= N_NODES) return;

    float dv = g_dinv[v];
    float4 xv = ((const float4*)(fin + (size_t)v * D_FEAT))[lane];
    float sl = dv * dv;
    float4 acc = make_float4(xv.x * sl, xv.y * sl, xv.z * sl, xv.w * sl);

    int j   = g_off[v];
    int end = g_off[v + 1];
    for (; j + 8 <= end; j += 8) {
        int2  e[8];
        float4 f[8];
#pragma unroll
        for (int q = 0; q < 8; q++) e[q] = g_csr[j + q];
#pragma unroll
        for (int q = 0; q < 8; q++)
            f[q] = ((const float4*)(fin + (size_t)e[q].x * D_FEAT))[lane];
#pragma unroll
        for (int q = 0; q < 8; q++) {
            float w = __int_as_float(e[q].y);
            acc.x += w * f[q].x; acc.y += w * f[q].y;
            acc.z += w * f[q].z; acc.w += w * f[q].w;
        }
    }
    for (; j < end; j++) {
        int2 e = g_csr[j];
        float w = __int_as_float(e.y);
        float4 f = ((const float4*)(fin + (size_t)e.x * D_FEAT))[lane];
        acc.x += w * f.x; acc.y += w * f.y; acc.z += w * f.z; acc.w += w * f.w;
    }
    ((float4*)(fout + (size_t)v * D_FEAT))[lane] = acc;
}

// ---------------- GEMM: C[M,BN] = A[M,128] @ W(128xBN) + bias (+relu), f32x2 ----------
// SRC 0: A = g_bufA, C = g_bufB (layer GEMMs).  SRC 1: A = g_bufB, C = outp (head).
template <int BN, bool RELU, int SRC>
__global__ void __launch_bounds__(256) k_gemm(const float* __restrict__ W,
                                              const float* __restrict__ bias,
                                              float* __restrict__ outp, int M) {
    const float* __restrict__ A = (SRC == 0) ? (const float*)g_bufA : (const float*)g_bufB;
    float* __restrict__ C = (SRC == 0) ? g_bufB : outp;

    constexpr int TN  = BN / 16;     // cols per thread (8 or 4)
    constexpr int TNP = TN / 2;      // packed pairs
    __shared__ float As[16][65];     // k-major A tile
    __shared__ float Bs[16][BN];

    const int t  = threadIdx.x;
    const int tx = t & 15;
    const int ty = t >> 4;
    const int m0 = blockIdx.x * 64;

    unsigned long long acc2[4][TNP];
#pragma unroll
    for (int i = 0; i < 4; i++)
#pragma unroll
        for (int j = 0; j < TNP; j++) acc2[i][j] = 0ull;

    for (int k0 = 0; k0 < 128; k0 += 16) {
        // A tile 64x16 -> k-major SMEM
        {
            int r  = t >> 2;
            int c  = (t & 3) * 4;
            int gm = m0 + r;
            float4 v = make_float4(0.f, 0.f, 0.f, 0.f);
            if (gm < M) v = *(const float4*)(A + (size_t)gm * 128 + k0 + c);
            As[c + 0][r] = v.x; As[c + 1][r] = v.y;
            As[c + 2][r] = v.z; As[c + 3][r] = v.w;
        }
        // B tile 16xBN
        {
            constexpr int F4 = 16 * BN / 4;
#pragma unroll
            for (int i = 0; i < F4 / 256; i++) {
                int idx = t + i * 256;
                int rr  = idx / (BN / 4);
                int cc  = (idx % (BN / 4)) * 4;
                *(float4*)&Bs[rr][cc] = *(const float4*)(W + (size_t)(k0 + rr) * BN + cc);
            }
        }
        __syncthreads();
#pragma unroll
        for (int kk = 0; kk < 16; kk++) {
            unsigned long long ap[4], bv[TNP];
#pragma unroll
            for (int i = 0; i < 4; i++) {
                float a = As[kk][ty * 4 + i];
                ap[i] = pack2(a, a);
            }
#pragma unroll
            for (int j = 0; j < TNP; j++)
                bv[j] = *(const unsigned long long*)&Bs[kk][tx * TN + 2 * j];
#pragma unroll
            for (int i = 0; i < 4; i++)
#pragma unroll
                for (int j = 0; j < TNP; j++) ffma2(acc2[i][j], ap[i], bv[j]);
        }
        __syncthreads();
    }

#pragma unroll
    for (int i = 0; i < 4; i++) {
        int gm = m0 + ty * 4 + i;
        if (gm >= M) continue;
        float o[TN];
#pragma unroll
        for (int j = 0; j < TNP; j++) {
            float lo, hi; unpack2(acc2[i][j], lo, hi);
            int col = tx * TN + 2 * j;
            lo += bias[col]; hi += bias[col + 1];
            if (RELU) { lo = fmaxf(lo, 0.f); hi = fmaxf(hi, 0.f); }
            o[2 * j] = lo; o[2 * j + 1] = hi;
        }
#pragma unroll
        for (int j = 0; j < TN; j += 4)
            *(float4*)(C + (size_t)gm * BN + tx * TN + j) =
                make_float4(o[j], o[j + 1], o[j + 2], o[j + 3]);
    }
}

// ---------------- launch ----------------
extern "C" void kernel_launch(void* const* d_in, const int* in_sizes, int n_in,
                              void* d_out, int out_size) {
    const float* x  = (const float*)d_in[0];
    const void*  ei = d_in[1];
    const float* w1 = (const float*)d_in[2];
    const float* b1 = (const float*)d_in[3];
    const float* w2 = (const float*)d_in[4];
    const float* b2 = (const float*)d_in[5];
    const float* w3 = (const float*)d_in[6];
    const float* b3 = (const float*)d_in[7];
    const float* wo = (const float*)d_in[8];
    const float* bo = (const float*)d_in[9];
    float* out = (float*)d_out;

    const int TB = 256;
    k_init   <<<(N_NODES + TB - 1) / TB, TB>>>((const int*)ei);
    k_hist   <<<(N_EDGES / 2 + TB - 1) / TB, TB>>>(ei);
    k_scan   <<<1, 1024>>>();
    k_scatter<<<(N_EDGES / 2 + TB - 1) / TB, TB>>>(ei);

    const int AGG_BLOCKS  = (N_NODES * 32 + TB - 1) / TB;   // one warp per node
    const int GEMM_BLOCKS = (N_NODES + 63) / 64;

    // layer 1: bufA = agg(x); bufB = relu(bufA @ W1 + b1)
    k_agg<<<AGG_BLOCKS, TB>>>(x);
    k_gemm<128, true, 0><<<GEMM_BLOCKS, TB>>>(w1, b1, nullptr, N_NODES);
    // layer 2
    k_agg<<<AGG_BLOCKS, TB>>>(nullptr);
    k_gemm<128, true, 0><<<GEMM_BLOCKS, TB>>>(w2, b2, nullptr, N_NODES);
    // layer 3
    k_agg<<<AGG_BLOCKS, TB>>>(nullptr);
    k_gemm<128, true, 0><<<GEMM_BLOCKS, TB>>>(w3, b3, nullptr, N_NODES);
    // head: out = bufB @ Wout + bout
    k_gemm<64, false, 1><<<GEMM_BLOCKS, TB>>>(wo, bo, out, N_NODES);
}

// round 6
// speedup vs baseline: 1.2412x; 1.0979x over previous
#include <cuda_runtime.h>
#include <cuda_fp16.h>

#define N_NODES 10000
#define N_EDGES 640000
#define D_FEAT  128

// ---------------- scratch (static device globals; no allocations) ----------------
__device__ __align__(256) float  g_dinv[N_NODES];
__device__ __align__(256) int    g_count[N_NODES];
__device__ __align__(256) int    g_cur[N_NODES];
__device__ __align__(256) int    g_off[N_NODES + 1];
__device__ __align__(256) int2   g_csr[N_EDGES];          // {src, float bits of weight}
__device__ __align__(256) float  g_bufA[N_NODES * D_FEAT]; // agg output (fp32, GEMM A)
__device__ __align__(256) float  g_bufB[N_NODES * D_FEAT]; // layer-3 fp32 output (head A)
__device__ __align__(256) __half g_bufH[N_NODES * D_FEAT]; // fp16 features (agg input)
__device__ int g_is64;

// ---------------- packed f32x2 helpers (sm_100a) ----------------
__device__ __forceinline__ unsigned long long pack2(float x, float y) {
    unsigned long long r;
    asm("mov.b64 %0, {%1, %2};" : "=l"(r) : "f"(x), "f"(y));
    return r;
}
__device__ __forceinline__ void unpack2(unsigned long long v, float& x, float& y) {
    asm("mov.b64 {%0, %1}, %2;" : "=f"(x), "=f"(y) : "l"(v));
}
__device__ __forceinline__ void ffma2(unsigned long long& c,
                                      unsigned long long a, unsigned long long b) {
    asm("fma.rn.f32x2 %0, %1, %2, %0;" : "+l"(c) : "l"(a), "l"(b));
}

// ---------------- structure kernels ----------------

// zero counters + dtype-detect (warp 0 of block 0).
// int64 edge_index => every odd 32-bit word of the src row is 0 (values < 2^31).
__global__ void k_init(const int* __restrict__ ei32) {
    int t = threadIdx.x;
    int i = blockIdx.x * blockDim.x + t;
    if (i < N_NODES) { g_count[i] = 0; g_cur[i] = 0; }
    if (blockIdx.x == 0 && t < 32) {
        int any = 0;
#pragma unroll 8
        for (int k = 0; k < 32; k++) any |= ei32[2 * (t * 32 + k) + 1];
        int is64 = __any_sync(0xffffffffu, any != 0) ? 0 : 1;
        if (t == 0) g_is64 = is64;
    }
}

__device__ __forceinline__ void load4(const void* ei, int base4, int row, int* v) {
    // load 4 consecutive indices from row (0=src,1=dst) starting at edge base4*4
    if (g_is64) {
        const longlong2* p = (const longlong2*)ei + row * (N_EDGES / 2) + base4 * 2;
        longlong2 a = p[0], b = p[1];
        v[0] = (int)a.x; v[1] = (int)a.y; v[2] = (int)b.x; v[3] = (int)b.y;
    } else {
        int4 a = ((const int4*)ei)[row * (N_EDGES / 4) + base4];
        v[0] = a.x; v[1] = a.y; v[2] = a.z; v[3] = a.w;
    }
}

// histogram of dst row, 4 edges per thread
__global__ void k_hist(const void* __restrict__ ei) {
    int i = blockIdx.x * blockDim.x + threadIdx.x;
    if (i < N_EDGES / 4) {
        int d[4];
        load4(ei, i, 1, d);
#pragma unroll
        for (int q = 0; q < 4; q++)
            if ((unsigned)d[q] < N_NODES) atomicAdd(&g_count[d[q]], 1);
    }
}

// single-block exclusive scan of g_count -> g_off, plus dinv
__global__ void k_scan() {
    __shared__ int part[1024];
    const int CH = 10;
    int t = threadIdx.x;
    int base = t * CH;
    int s = 0;
#pragma unroll
    for (int i = 0; i < CH; i++) {
        int idx = base + i;
        if (idx < N_NODES) s += g_count[idx];
    }
    part[t] = s;
    __syncthreads();
    for (int d = 1; d < 1024; d <<= 1) {
        int v = (t >= d) ? part[t - d] : 0;
        __syncthreads();
        part[t] += v;
        __syncthreads();
    }
    int run = (t == 0) ? 0 : part[t - 1];
#pragma unroll
    for (int i = 0; i < CH; i++) {
        int idx = base + i;
        if (idx < N_NODES) {
            int c = g_count[idx];
            g_off[idx] = run;
            run += c;
            g_dinv[idx] = rsqrtf((float)(c + 1));   // +1 self-loop
        } else if (idx == N_NODES) {
            g_off[N_NODES] = run;
        }
    }
}

// CSR fill, 4 edges per thread
__global__ void k_scatter(const void* __restrict__ ei) {
    int i = blockIdx.x * blockDim.x + threadIdx.x;
    if (i < N_EDGES / 4) {
        int s[4], d[4];
        load4(ei, i, 0, s);
        load4(ei, i, 1, d);
#pragma unroll
        for (int q = 0; q < 4; q++) {
            if ((unsigned)d[q] < N_NODES) {
                int p = g_off[d[q]] + atomicAdd(&g_cur[d[q]], 1);
                bool sv = (unsigned)s[q] < N_NODES;
                float w = sv ? (g_dinv[s[q]] * g_dinv[d[q]]) : 0.0f;
                g_csr[p] = make_int2(sv ? s[q] : 0, __float_as_int(w));
            }
        }
    }
}

// ---------------- convert external x (fp32) -> g_bufH (fp16) ----------------
__global__ void k_cvt(const float* __restrict__ x) {
    int i = blockIdx.x * blockDim.x + threadIdx.x;  // 4 floats per thread
    if (i < N_NODES * D_FEAT / 4) {
        float4 v = ((const float4*)x)[i];
        __half2 h0 = __floats2half2_rn(v.x, v.y);
        __half2 h1 = __floats2half2_rn(v.z, v.w);
        uint2 u;
        u.x = *(unsigned*)&h0;
        u.y = *(unsigned*)&h1;
        ((uint2*)g_bufH)[i] = u;
    }
}

// ---------------- aggregation: one warp per destination node ----------------
// out[v] = dinv[v]^2 * in[v] + sum_e w_e * in[src_e]
// Input: g_bufH (fp16). Output: g_bufA (fp32). Lane covers 4 feats (uint2 = 4 halves).
__global__ void __launch_bounds__(256) k_agg() {
    const __half* __restrict__ fin = g_bufH;
    float* __restrict__ fout = g_bufA;

    int v    = (blockIdx.x * blockDim.x + threadIdx.x) >> 5;
    int lane = threadIdx.x & 31;
    if (v >= N_NODES) return;

    float dv = g_dinv[v];
    float sl = dv * dv;

    uint2 ux = ((const uint2*)(fin + (size_t)v * D_FEAT))[lane];
    float2 x0 = __half22float2(*(__half2*)&ux.x);
    float2 x1 = __half22float2(*(__half2*)&ux.y);
    float4 acc = make_float4(x0.x * sl, x0.y * sl, x1.x * sl, x1.y * sl);

    int j   = g_off[v];
    int end = g_off[v + 1];
    for (; j + 8 <= end; j += 8) {
        int2 e[8];
        uint2 u[8];
#pragma unroll
        for (int q = 0; q < 8; q++) e[q] = g_csr[j + q];
#pragma unroll
        for (int q = 0; q < 8; q++)
            u[q] = ((const uint2*)(fin + (size_t)e[q].x * D_FEAT))[lane];
#pragma unroll
        for (int q = 0; q < 8; q++) {
            float w = __int_as_float(e[q].y);
            float2 f0 = __half22float2(*(__half2*)&u[q].x);
            float2 f1 = __half22float2(*(__half2*)&u[q].y);
            acc.x += w * f0.x; acc.y += w * f0.y;
            acc.z += w * f1.x; acc.w += w * f1.y;
        }
    }
    for (; j < end; j++) {
        int2 e = g_csr[j];
        float w = __int_as_float(e.y);
        uint2 u = ((const uint2*)(fin + (size_t)e.x * D_FEAT))[lane];
        float2 f0 = __half22float2(*(__half2*)&u.x);
        float2 f1 = __half22float2(*(__half2*)&u.y);
        acc.x += w * f0.x; acc.y += w * f0.y;
        acc.z += w * f1.x; acc.w += w * f1.y;
    }
    ((float4*)(fout + (size_t)v * D_FEAT))[lane] = acc;
}

// ---------------- GEMM: C[M,BN] = A[M,128] @ W(128xBN) + bias (+relu), f32x2 ----------
// SRC 0: A = g_bufA. SRC 1: A = g_bufB.
// DST 0: fp16 -> g_bufH. DST 1: fp32 -> g_bufB. DST 2: fp32 -> outp.
template <int BN, bool RELU, int SRC, int DST>
__global__ void __launch_bounds__(256) k_gemm(const float* __restrict__ W,
                                              const float* __restrict__ bias,
                                              float* __restrict__ outp, int M) {
    const float* __restrict__ A = (SRC == 0) ? (const float*)g_bufA : (const float*)g_bufB;

    constexpr int TN  = BN / 16;     // cols per thread (8 or 4)
    constexpr int TNP = TN / 2;      // packed pairs
    __shared__ float As[16][65];     // k-major A tile
    __shared__ float Bs[16][BN];

    const int t  = threadIdx.x;
    const int tx = t & 15;
    const int ty = t >> 4;
    const int m0 = blockIdx.x * 64;

    unsigned long long acc2[4][TNP];
#pragma unroll
    for (int i = 0; i < 4; i++)
#pragma unroll
        for (int j = 0; j < TNP; j++) acc2[i][j] = 0ull;

    for (int k0 = 0; k0 < 128; k0 += 16) {
        // A tile 64x16 -> k-major SMEM
        {
            int r  = t >> 2;
            int c  = (t & 3) * 4;
            int gm = m0 + r;
            float4 v = make_float4(0.f, 0.f, 0.f, 0.f);
            if (gm < M) v = *(const float4*)(A + (size_t)gm * 128 + k0 + c);
            As[c + 0][r] = v.x; As[c + 1][r] = v.y;
            As[c + 2][r] = v.z; As[c + 3][r] = v.w;
        }
        // B tile 16xBN
        {
            constexpr int F4 = 16 * BN / 4;
#pragma unroll
            for (int i = 0; i < F4 / 256; i++) {
                int idx = t + i * 256;
                int rr  = idx / (BN / 4);
                int cc  = (idx % (BN / 4)) * 4;
                *(float4*)&Bs[rr][cc] = *(const float4*)(W + (size_t)(k0 + rr) * BN + cc);
            }
        }
        __syncthreads();
#pragma unroll
        for (int kk = 0; kk < 16; kk++) {
            unsigned long long ap[4], bv[TNP];
#pragma unroll
            for (int i = 0; i < 4; i++) {
                float a = As[kk][ty * 4 + i];
                ap[i] = pack2(a, a);
            }
#pragma unroll
            for (int j = 0; j < TNP; j++)
                bv[j] = *(const unsigned long long*)&Bs[kk][tx * TN + 2 * j];
#pragma unroll
            for (int i = 0; i < 4; i++)
#pragma unroll
                for (int j = 0; j < TNP; j++) ffma2(acc2[i][j], ap[i], bv[j]);
        }
        __syncthreads();
    }

#pragma unroll
    for (int i = 0; i < 4; i++) {
        int gm = m0 + ty * 4 + i;
        if (gm >= M) continue;
        float o[TN];
#pragma unroll
        for (int j = 0; j < TNP; j++) {
            float lo, hi; unpack2(acc2[i][j], lo, hi);
            int col = tx * TN + 2 * j;
            lo += bias[col]; hi += bias[col + 1];
            if (RELU) { lo = fmaxf(lo, 0.f); hi = fmaxf(hi, 0.f); }
            o[2 * j] = lo; o[2 * j + 1] = hi;
        }
        if (DST == 0) {
            // fp16 output (TN==8): 8 halves = 16 bytes = one uint4
            __half2 h0 = __floats2half2_rn(o[0], o[1]);
            __half2 h1 = __floats2half2_rn(o[2], o[3]);
            __half2 h2 = __floats2half2_rn(o[4], o[5]);
            __half2 h3 = __floats2half2_rn(o[6], o[7]);
            uint4 u;
            u.x = *(unsigned*)&h0; u.y = *(unsigned*)&h1;
            u.z = *(unsigned*)&h2; u.w = *(unsigned*)&h3;
            *(uint4*)(g_bufH + (size_t)gm * 128 + tx * 8) = u;
        } else {
            float* __restrict__ C = (DST == 1) ? g_bufB : outp;
#pragma unroll
            for (int j = 0; j < TN; j += 4)
                *(float4*)(C + (size_t)gm * BN + tx * TN + j) =
                    make_float4(o[j], o[j + 1], o[j + 2], o[j + 3]);
        }
    }
}

// ---------------- launch ----------------
extern "C" void kernel_launch(void* const* d_in, const int* in_sizes, int n_in,
                              void* d_out, int out_size) {
    const float* x  = (const float*)d_in[0];
    const void*  ei = d_in[1];
    const float* w1 = (const float*)d_in[2];
    const float* b1 = (const float*)d_in[3];
    const float* w2 = (const float*)d_in[4];
    const float* b2 = (const float*)d_in[5];
    const float* w3 = (const float*)d_in[6];
    const float* b3 = (const float*)d_in[7];
    const float* wo = (const float*)d_in[8];
    const float* bo = (const float*)d_in[9];
    float* out = (float*)d_out;

    const int TB = 256;
    k_init   <<<(N_NODES + TB - 1) / TB, TB>>>((const int*)ei);
    k_hist   <<<(N_EDGES / 4 + TB - 1) / TB, TB>>>(ei);
    k_scan   <<<1, 1024>>>();
    k_scatter<<<(N_EDGES / 4 + TB - 1) / TB, TB>>>(ei);
    k_cvt    <<<(N_NODES * D_FEAT / 4 + TB - 1) / TB, TB>>>(x);

    const int AGG_BLOCKS  = (N_NODES * 32 + TB - 1) / TB;   // one warp per node
    const int GEMM_BLOCKS = (N_NODES + 63) / 64;

    // layer 1: bufA = agg(H); H = relu(bufA @ W1 + b1) [fp16]
    k_agg<<<AGG_BLOCKS, TB>>>();
    k_gemm<128, true, 0, 0><<<GEMM_BLOCKS, TB>>>(w1, b1, nullptr, N_NODES);
    // layer 2
    k_agg<<<AGG_BLOCKS, TB>>>();
    k_gemm<128, true, 0, 0><<<GEMM_BLOCKS, TB>>>(w2, b2, nullptr, N_NODES);
    // layer 3: bufB = relu(agg @ W3 + b3) [fp32]
    k_agg<<<AGG_BLOCKS, TB>>>();
    k_gemm<128, true, 0, 1><<<GEMM_BLOCKS, TB>>>(w3, b3, nullptr, N_NODES);
    // head: out = bufB @ Wout + bout
    k_gemm<64, false, 1, 2><<<GEMM_BLOCKS, TB>>>(wo, bo, out, N_NODES);
}